// round 16
// baseline (speedup 1.0000x reference)
#include <cuda_runtime.h>
#include <cuda_fp16.h>
#include <mma.h>
#include <math.h>
#include <stdint.h>

using namespace nvcuda;

#define BB 4
#define SS 1024
#define DD 256
#define HH 512
#define NTY 20
#define NSAMP 50
#define NROWS (BB*SS)          /* 4096 */
#define MROWS (NROWS*NSAMP)    /* 204800 */

// ---------------- scratch (static device globals; no runtime allocation) ----------------
__device__ __half g_hv_h[NROWS*HH];      // [pe, temb] per event, fp16
__device__ float  g_hidden[NROWS*HH];    // aggregated hidden (j-tiles 0..7)
__device__ float  g_hidden2[NROWS*HH];   // aggregated hidden (j-tiles 8..15)
__device__ __half g_hn_h[NROWS*HH];      // layernormed hidden (fp16)
__device__ float  g_c[NROWS*HH];         // hn @ w_in^T
__device__ float  g_sdot4[MROWS*4];      // per-(row, n-tile) partial  h.w_time
__device__ float  g_as[NROWS], g_bs[NROWS], g_ag[NROWS], g_bg[NROWS];
__device__ __half g_win_h[HH*HH];        // fp16 copy of w_in
__device__ __half g_wn_h[HH*HH];         // fp16 copy of w_noise

static __device__ __forceinline__ unsigned h2u(__half2 h){ return *reinterpret_cast<unsigned*>(&h); }

// ============================== K0: weight fp32->fp16 pre-convert ==============================
__global__ __launch_bounds__(256)
void k0_wconv(const float* __restrict__ win, const float* __restrict__ wnoise)
{
    int i = (blockIdx.x*256 + threadIdx.x) * 4;
    if (i < HH*HH){
        float4 a = *reinterpret_cast<const float4*>(&win[i]);
        float4 b = *reinterpret_cast<const float4*>(&wnoise[i]);
        __half2 a0 = __floats2half2_rn(a.x,a.y), a1 = __floats2half2_rn(a.z,a.w);
        __half2 b0 = __floats2half2_rn(b.x,b.y), b1 = __floats2half2_rn(b.z,b.w);
        uint2 va; va.x=h2u(a0); va.y=h2u(a1);
        uint2 vb; vb.x=h2u(b0); vb.y=h2u(b1);
        *reinterpret_cast<uint2*>(&g_win_h[i]) = va;
        *reinterpret_cast<uint2*>(&g_wn_h[i])  = vb;
    }
}

// ============================== K1: embeddings + per-event projections ==============================
__global__ __launch_bounds__(128)
void k1_embed(const int* __restrict__ etype, const float* __restrict__ etime,
              const float* __restrict__ wt, const float* __restrict__ table,
              const float* __restrict__ wsig, const float* __restrict__ wgate)
{
    int row = blockIdx.x;
    int j = threadIdx.x;          // 0..127
    int s = row & (SS-1);
    int ty = etype[row];
    float t = etime[row];
    float e0 = table[ty*DD + j];
    float e1 = table[ty*DD + 128 + j];
    const float kc = -9.210340371976184f / (float)DD;   // -ln(10000)/d
    float dt = __expf((float)(2*j) * kc);
    float arc = (float)s * dt + t * wt[j];
    size_t base = (size_t)row * HH;
    g_hv_h[base + j]       = __float2half_rn(sinf(arc));
    g_hv_h[base + 128 + j] = __float2half_rn(cosf(arc));
    g_hv_h[base + 256 + j] = __float2half_rn(e0);
    g_hv_h[base + 384 + j] = __float2half_rn(e1);
    float pas = e0*wsig[j]      + e1*wsig[128+j];
    float pbs = e0*wsig[256+j]  + e1*wsig[384+j];
    float pag = e0*wgate[j]     + e1*wgate[128+j];
    float pbg = e0*wgate[256+j] + e1*wgate[384+j];
    __shared__ float r4[4][4];
    #pragma unroll
    for (int o=16;o>0;o>>=1){
        pas += __shfl_xor_sync(0xffffffffu, pas, o);
        pbs += __shfl_xor_sync(0xffffffffu, pbs, o);
        pag += __shfl_xor_sync(0xffffffffu, pag, o);
        pbg += __shfl_xor_sync(0xffffffffu, pbg, o);
    }
    if ((j&31)==0){ int w=j>>5; r4[w][0]=pas; r4[w][1]=pbs; r4[w][2]=pag; r4[w][3]=pbg; }
    __syncthreads();
    if (j==0){
        g_as[row]=r4[0][0]+r4[1][0]+r4[2][0]+r4[3][0];
        g_bs[row]=r4[0][1]+r4[1][1]+r4[2][1]+r4[3][1];
        g_ag[row]=r4[0][2]+r4[1][2]+r4[2][2]+r4[3][2];
        g_bg[row]=r4[0][3]+r4[1][3]+r4[2][3]+r4[3][3];
    }
}

// ============================== K2: scores + aggregation via WMMA, j-split ==============================
__global__ __launch_bounds__(256)
void k2_aggregate(const float* __restrict__ etime)
{
    __shared__ __align__(16) __half Sh[64][72];
    __shared__ __align__(16) __half HV[64][264];
    __shared__ float asj[64], agj[64], tjv[64];
    __shared__ float bsi[64], bgi[64], tiv[64];

    const int tid = threadIdx.x;
    const int it = blockIdx.x;
    const int b  = blockIdx.y;
    const int hbase  = (blockIdx.z & 1) * 256;
    const int jhalf  = blockIdx.z >> 1;
    const int rowbase = b * SS;
    const int ibase = it * 64;

    if (tid < 64){
        int gi = rowbase + ibase + tid;
        bsi[tid]=g_bs[gi]; bgi[tid]=g_bg[gi]; tiv[tid]=etime[gi];
    }

    const int warp = tid>>5;
    const int wr = warp>>2;
    const int wc = warp&3;

    wmma::fragment<wmma::accumulator,16,16,16,float> acc[2][4];
    #pragma unroll
    for (int f=0;f<2;f++)
      #pragma unroll
      for (int g=0;g<4;g++) wmma::fill_fragment(acc[f][g], 0.f);

    const int il = tid>>2;
    const int jq = (tid&3)*16;
    const int hrow = tid>>2;
    const int hc4 = tid&3;

    const int j0 = jhalf * 8;
    const int j1 = jhalf ? it : ((it < 7) ? it : 7);

    for (int jt = j0; jt <= j1; jt++){
        if (tid < 64){
            int gj = rowbase + jt*64 + tid;
            asj[tid]=g_as[gj]; agj[tid]=g_ag[gj]; tjv[tid]=etime[gj];
        }
        __syncthreads();
        {
            const __half* src = &g_hv_h[(size_t)(rowbase + jt*64 + hrow)*HH + hbase];
            #pragma unroll
            for (int u=0;u<8;u++){
                int c16 = hc4 + u*4;
                unsigned sa = (unsigned)__cvta_generic_to_shared(&HV[hrow][c16*8]);
                asm volatile("cp.async.cg.shared.global [%0], [%1], 16;\n" :: "r"(sa), "l"(src + c16*8));
            }
            asm volatile("cp.async.commit_group;\n");
        }
        {
            float bs_i = bsi[il], bg_i = bgi[il], t_i = tiv[il];
            bool diag = (jt == it);
            #pragma unroll
            for (int q=0;q<16;q++){
                int jl = jq + q;
                float sv = 0.f;
                if (!diag || (jl < il)){
                    float xg = agj[jl] + bg_i;
                    float gate = 1.f/(1.f+__expf(-xg));
                    float xs = asj[jl] + bs_i;
                    float sig = (xs > 20.f) ? xs : log1pf(__expf(xs));
                    float dtv = fabsf(t_i - tjv[jl]);
                    sv = gate * __expf(-sig*dtv);
                }
                Sh[il][jl] = __float2half_rn(sv);
            }
        }
        asm volatile("cp.async.wait_group 0;\n");
        __syncthreads();
        #pragma unroll
        for (int kk=0;kk<4;kk++){
            wmma::fragment<wmma::matrix_a,16,16,16,__half,wmma::row_major> af[2];
            wmma::fragment<wmma::matrix_b,16,16,16,__half,wmma::row_major> bf[4];
            #pragma unroll
            for (int f=0;f<2;f++)
                wmma::load_matrix_sync(af[f], &Sh[wr*32 + f*16][kk*16], 72);
            #pragma unroll
            for (int g=0;g<4;g++)
                wmma::load_matrix_sync(bf[g], &HV[kk*16][wc*64 + g*16], 264);
            #pragma unroll
            for (int f=0;f<2;f++)
              #pragma unroll
              for (int g=0;g<4;g++)
                wmma::mma_sync(acc[f][g], af[f], bf[g], acc[f][g]);
        }
    }
    float* dst0 = jhalf ? g_hidden2 : g_hidden;
    #pragma unroll
    for (int f=0;f<2;f++)
      #pragma unroll
      for (int g=0;g<4;g++)
        wmma::store_matrix_sync(&dst0[(size_t)(rowbase + ibase + wr*32 + f*16)*HH + hbase + wc*64 + g*16],
                                acc[f][g], HH, wmma::mem_row_major);
}

// ============================== K3: LayerNorm + mark_probs softmax ==============================
__global__ __launch_bounds__(256)
void k3_ln_pred(const float* __restrict__ gamma, const float* __restrict__ beta,
                const float* __restrict__ wpred, float* __restrict__ out_probs)
{
    int row = blockIdx.x, tid = threadIdx.x, lane = tid&31, w = tid>>5;
    size_t base = (size_t)row*HH;
    float x0 = g_hidden[base+tid]     + g_hidden2[base+tid];
    float x1 = g_hidden[base+256+tid] + g_hidden2[base+256+tid];
    __shared__ float red[8];
    float sv = x0+x1;
    #pragma unroll
    for (int o=16;o>0;o>>=1) sv += __shfl_xor_sync(0xffffffffu, sv, o);
    if (lane==0) red[w]=sv;
    __syncthreads();
    float mu=0.f;
    #pragma unroll
    for (int i=0;i<8;i++) mu+=red[i];
    mu *= (1.f/HH);
    float d0=x0-mu, d1=x1-mu;
    float vv = d0*d0+d1*d1;
    __syncthreads();
    #pragma unroll
    for (int o=16;o>0;o>>=1) vv += __shfl_xor_sync(0xffffffffu, vv, o);
    if (lane==0) red[w]=vv;
    __syncthreads();
    float var=0.f;
    #pragma unroll
    for (int i=0;i<8;i++) var+=red[i];
    var *= (1.f/HH);
    float rstd = rsqrtf(var + 1e-6f);
    float hn0 = d0*rstd*gamma[tid] + beta[tid];
    float hn1 = d1*rstd*gamma[256+tid] + beta[256+tid];
    g_hn_h[base+tid]     = __float2half_rn(hn0);
    g_hn_h[base+256+tid] = __float2half_rn(hn1);
    float pl[NTY];
    #pragma unroll
    for (int o=0;o<NTY;o++)
        pl[o] = hn0*wpred[o*HH+tid] + hn1*wpred[o*HH+256+tid];
    __shared__ float lred[8][NTY];
    #pragma unroll
    for (int o=0;o<NTY;o++){
        float p = pl[o];
        #pragma unroll
        for (int s=16;s>0;s>>=1) p += __shfl_xor_sync(0xffffffffu, p, s);
        if (lane==0) lred[w][o]=p;
    }
    __syncthreads();
    if (tid < 32){
        float l = -1e30f;
        if (tid < NTY){
            l = 0.f;
            #pragma unroll
            for (int i=0;i<8;i++) l += lred[i][tid];
        }
        float mx = l;
        #pragma unroll
        for (int o=16;o>0;o>>=1) mx = fmaxf(mx, __shfl_xor_sync(0xffffffffu, mx, o));
        float e = (tid<NTY) ? expf(l-mx) : 0.f;
        float se = e;
        #pragma unroll
        for (int o=16;o>0;o>>=1) se += __shfl_xor_sync(0xffffffffu, se, o);
        if (tid<NTY) out_probs[(size_t)row*NTY + tid] = e/se;
    }
}

// ============================== K4: small GEMM g_c = hn @ w_in^T (WMMA, cp.async) ==============================
__global__ __launch_bounds__(256, 2)
void gemm_c()
{
    __shared__ __align__(16) __half As[2][128][40];
    __shared__ __align__(16) __half Bs[2][128][40];

    const int tid  = threadIdx.x;
    const int warp = tid>>5;
    const int wm = warp>>2;
    const int wn = warp&3;
    const int n_cta = blockIdx.x * 128;
    const int m_cta = blockIdx.y * 128;

    const int br = tid >> 2;
    const int bc = (tid & 3) * 8;

    wmma::fragment<wmma::accumulator,16,16,16,float> acc[4][2];
    #pragma unroll
    for (int i=0;i<4;i++)
      #pragma unroll
      for (int jx=0;jx<2;jx++) wmma::fill_fragment(acc[i][jx], 0.f);

    #pragma unroll
    for (int i=0;i<2;i++){
        unsigned sb = (unsigned)__cvta_generic_to_shared(&Bs[0][br+64*i][bc]);
        asm volatile("cp.async.cg.shared.global [%0], [%1], 16;\n" :: "r"(sb), "l"(&g_win_h[(size_t)(n_cta + br + 64*i)*HH + bc]));
        unsigned sa = (unsigned)__cvta_generic_to_shared(&As[0][br+64*i][bc]);
        asm volatile("cp.async.cg.shared.global [%0], [%1], 16;\n" :: "r"(sa), "l"(&g_hn_h[(size_t)(m_cta + br + 64*i)*HH + bc]));
    }
    asm volatile("cp.async.commit_group;\n");
    asm volatile("cp.async.wait_group 0;\n");
    __syncthreads();

    #pragma unroll 1
    for (int kc=0; kc<16; kc++){
        const int cur = kc & 1;
        const int nxt = cur ^ 1;
        if (kc < 15){
            int k0 = (kc+1)*32;
            #pragma unroll
            for (int i=0;i<2;i++){
                unsigned sb = (unsigned)__cvta_generic_to_shared(&Bs[nxt][br+64*i][bc]);
                asm volatile("cp.async.cg.shared.global [%0], [%1], 16;\n" :: "r"(sb), "l"(&g_win_h[(size_t)(n_cta + br + 64*i)*HH + k0 + bc]));
                unsigned sa = (unsigned)__cvta_generic_to_shared(&As[nxt][br+64*i][bc]);
                asm volatile("cp.async.cg.shared.global [%0], [%1], 16;\n" :: "r"(sa), "l"(&g_hn_h[(size_t)(m_cta + br + 64*i)*HH + k0 + bc]));
            }
            asm volatile("cp.async.commit_group;\n");
        }
        #pragma unroll
        for (int ks=0; ks<2; ks++){
            wmma::fragment<wmma::matrix_a,16,16,16,__half,wmma::row_major> af[4];
            wmma::fragment<wmma::matrix_b,16,16,16,__half,wmma::col_major> bf[2];
            #pragma unroll
            for (int jx=0;jx<2;jx++)
                wmma::load_matrix_sync(bf[jx], &Bs[cur][wn*32 + jx*16][ks*16], 40);
            #pragma unroll
            for (int i=0;i<4;i++){
                wmma::load_matrix_sync(af[i], &As[cur][wm*64 + i*16][ks*16], 40);
                #pragma unroll
                for (int jx=0;jx<2;jx++)
                    wmma::mma_sync(acc[i][jx], af[i], bf[jx], acc[i][jx]);
            }
        }
        if (kc < 15){
            asm volatile("cp.async.wait_group 0;\n");
            __syncthreads();
        }
    }

    #pragma unroll
    for (int i=0;i<4;i++)
      #pragma unroll
      for (int jx=0;jx<2;jx++)
        wmma::store_matrix_sync(&g_c[(size_t)(m_cta + wm*64 + i*16)*HH + n_cta + wn*32 + jx*16],
                                acc[i][jx], HH, wmma::mem_row_major);
}

// ============================== K5: noise GEMM, 4 warps, warp tile 64x64 ==============================
// CTA 128(M)x128(N), K chunks of 32, 2-stage. A: fp32 LDG->cvt->STS; B: cp.async fp16.
// Epilogue: warp-private slab drain, smem-resident g_c/wtime, atomicAdd row partials.
__global__ __launch_bounds__(128, 2)
void gemm_noise(const float* __restrict__ A32, const float* __restrict__ wtime)
{
    __shared__ __align__(16) __half As[2][128][40];
    __shared__ __align__(16) __half Bs[2][128][40];
    __shared__ __align__(16) float slab[4][16][20];
    __shared__ float gcs[4][128];
    __shared__ float wts[128];
    __shared__ float sred[128];

    const int tid  = threadIdx.x;
    const int warp = tid>>5;
    const int lane = tid&31;
    const int wm = warp>>1;       // 0..1  (64 M-rows)
    const int wn = warp&1;        // 0..1  (64 N-cols)
    const int nx = blockIdx.x;            // 0..3
    const int n_cta = nx * 128;
    const int m_cta = blockIdx.y * 128;

    if (tid < 128) sred[tid] = 0.f;

    wmma::fragment<wmma::accumulator,16,16,16,float> acc[4][4];
    #pragma unroll
    for (int i=0;i<4;i++)
      #pragma unroll
      for (int j=0;j<4;j++) wmma::fill_fragment(acc[i][j], 0.f);

    float4 ra[8];

    // ---- prologue: chunk 0 ----
    {
        // B: 128 rows x 32 halfs, row = tid, 4x16B
        #pragma unroll
        for (int u=0;u<4;u++){
            unsigned sb = (unsigned)__cvta_generic_to_shared(&Bs[0][tid][u*8]);
            asm volatile("cp.async.cg.shared.global [%0], [%1], 16;\n" :: "r"(sb), "l"(&g_wn_h[(size_t)(n_cta + tid)*HH + u*8]));
        }
        asm volatile("cp.async.commit_group;\n");
        // A: row = tid, 32 fp32
        const float* src = &A32[(size_t)(m_cta + tid)*HH];
        #pragma unroll
        for (int u=0;u<8;u++) ra[u] = *reinterpret_cast<const float4*>(src + u*4);
        #pragma unroll
        for (int u=0;u<4;u++){
            uint4 hv;
            hv.x = h2u(__floats2half2_rn(ra[2*u].x, ra[2*u].y));
            hv.y = h2u(__floats2half2_rn(ra[2*u].z, ra[2*u].w));
            hv.z = h2u(__floats2half2_rn(ra[2*u+1].x, ra[2*u+1].y));
            hv.w = h2u(__floats2half2_rn(ra[2*u+1].z, ra[2*u+1].w));
            *reinterpret_cast<uint4*>(&As[0][tid][u*8]) = hv;
        }
        asm volatile("cp.async.wait_group 0;\n");
    }
    __syncthreads();

    #pragma unroll 1
    for (int kc=0; kc<16; kc++){
        const int cur = kc & 1;
        const int nxt = cur ^ 1;
        if (kc < 15){
            int k0 = (kc+1)*32;
            #pragma unroll
            for (int u=0;u<4;u++){
                unsigned sb = (unsigned)__cvta_generic_to_shared(&Bs[nxt][tid][u*8]);
                asm volatile("cp.async.cg.shared.global [%0], [%1], 16;\n" :: "r"(sb), "l"(&g_wn_h[(size_t)(n_cta + tid)*HH + k0 + u*8]));
            }
            asm volatile("cp.async.commit_group;\n");
            const float* src = &A32[(size_t)(m_cta + tid)*HH + k0];
            #pragma unroll
            for (int u=0;u<8;u++) ra[u] = *reinterpret_cast<const float4*>(src + u*4);
        }
        #pragma unroll
        for (int ks=0; ks<2; ks++){
            wmma::fragment<wmma::matrix_b,16,16,16,__half,wmma::col_major> bf[4];
            #pragma unroll
            for (int j=0;j<4;j++)
                wmma::load_matrix_sync(bf[j], &Bs[cur][wn*64 + j*16][ks*16], 40);
            #pragma unroll
            for (int i=0;i<4;i++){
                wmma::fragment<wmma::matrix_a,16,16,16,__half,wmma::row_major> af;
                wmma::load_matrix_sync(af, &As[cur][wm*64 + i*16][ks*16], 40);
                #pragma unroll
                for (int j=0;j<4;j++)
                    wmma::mma_sync(acc[i][j], af, bf[j], acc[i][j]);
            }
        }
        if (kc < 15){
            #pragma unroll
            for (int u=0;u<4;u++){
                uint4 hv;
                hv.x = h2u(__floats2half2_rn(ra[2*u].x, ra[2*u].y));
                hv.y = h2u(__floats2half2_rn(ra[2*u].z, ra[2*u].w));
                hv.z = h2u(__floats2half2_rn(ra[2*u+1].x, ra[2*u+1].y));
                hv.w = h2u(__floats2half2_rn(ra[2*u+1].z, ra[2*u+1].w));
                *reinterpret_cast<uint4*>(&As[nxt][tid][u*8]) = hv;
            }
            asm volatile("cp.async.wait_group 0;\n");
            __syncthreads();
        }
    }

    // ---- preload g_c rows + wtime for this CTA's column slice ----
    const int bs0 = m_cta / NSAMP;
    if (tid < 128) wts[tid] = wtime[n_cta + tid];
    #pragma unroll
    for (int q=0;q<4;q++){
        int bi = q;
        int row = bs0 + bi; if (row > NROWS-1) row = NROWS-1;
        gcs[bi][tid] = g_c[(size_t)row*HH + n_cta + tid];
    }
    __syncthreads();

    // ---- epilogue: warp-private drain, no block barriers until the end ----
    const int r = lane >> 1;
    const int hsel = (lane & 1) * 8;
    #pragma unroll
    for (int i=0;i<4;i++){
        int grow = m_cta + wm*64 + i*16 + r;
        int bi = grow / NSAMP - bs0;
        float vacc = 0.f;
        #pragma unroll
        for (int j=0;j<4;j++){
            wmma::store_matrix_sync(&slab[warp][0][0], acc[i][j], 20, wmma::mem_row_major);
            __syncwarp();
            #pragma unroll
            for (int c=0;c<8;c++){
                int col = wn*64 + j*16 + hsel + c;
                float h = slab[warp][r][hsel + c] + gcs[bi][col];
                vacc += fmaxf(h, 0.f) * wts[col];
            }
            __syncwarp();
        }
        vacc += __shfl_xor_sync(0xffffffffu, vacc, 1);
        if ((lane & 1) == 0) atomicAdd(&sred[wm*64 + i*16 + r], vacc);
    }
    __syncthreads();
    if (tid < 128)
        g_sdot4[(size_t)(m_cta + tid)*4 + nx] = sred[tid];
}

// ============================== K6: softplus + mean over samples ==============================
__global__ void k6_pred(float* __restrict__ out)
{
    int bs = blockIdx.x*blockDim.x + threadIdx.x;
    if (bs >= NROWS) return;
    float acc = 0.f;
    for (int n=0;n<NSAMP;n++){
        const float4 v = *reinterpret_cast<const float4*>(&g_sdot4[(size_t)(bs*NSAMP+n)*4]);
        float x = (v.x+v.y)+(v.z+v.w);
        float sp = (x > 20.f) ? x : log1pf(expf(x));
        acc += sp;
    }
    out[bs] = acc * (1.f/NSAMP);
}

// ============================== launch ==============================
extern "C" void kernel_launch(void* const* d_in, const int* in_sizes, int n_in,
                              void* d_out, int out_size) {
    const int*   etype  = (const int*)  d_in[0];
    const float* etime  = (const float*)d_in[1];
    const float* noise  = (const float*)d_in[2];
    const float* wt     = (const float*)d_in[3];
    const float* table  = (const float*)d_in[4];
    const float* wsig   = (const float*)d_in[5];
    const float* wgate  = (const float*)d_in[6];
    const float* lng    = (const float*)d_in[7];
    const float* lnb    = (const float*)d_in[8];
    const float* wpred  = (const float*)d_in[9];
    const float* win    = (const float*)d_in[10];
    const float* wnoise = (const float*)d_in[11];
    const float* wtime  = (const float*)d_in[12];
    float* out = (float*)d_out;

    k0_wconv<<<HH*HH/(256*4),256>>>(win, wnoise);
    k1_embed<<<NROWS,128>>>(etype, etime, wt, table, wsig, wgate);
    k2_aggregate<<<dim3(16,BB,4),256>>>(etime);
    k3_ln_pred<<<NROWS,256>>>(lng, lnb, wpred, out + NROWS);
    gemm_c<<<dim3(4, NROWS/128),256>>>();
    gemm_noise<<<dim3(4, MROWS/128),128>>>(noise, wtime);
    k6_pred<<<NROWS/128,128>>>(out);
}

// round 17
// speedup vs baseline: 1.3972x; 1.3972x over previous
#include <cuda_runtime.h>
#include <cuda_fp16.h>
#include <mma.h>
#include <math.h>
#include <stdint.h>

using namespace nvcuda;

#define BB 4
#define SS 1024
#define DD 256
#define HH 512
#define NTY 20
#define NSAMP 50
#define NROWS (BB*SS)          /* 4096 */
#define MROWS (NROWS*NSAMP)    /* 204800 */

// ---------------- scratch (static device globals; no runtime allocation) ----------------
__device__ __half g_hv_h[NROWS*HH];      // [pe, temb] per event, fp16
__device__ float  g_hidden[NROWS*HH];    // aggregated hidden (j-tiles 0..7)
__device__ float  g_hidden2[NROWS*HH];   // aggregated hidden (j-tiles 8..15)
__device__ __half g_hn_h[NROWS*HH];      // layernormed hidden (fp16)
__device__ float  g_c[NROWS*HH];         // hn @ w_in^T
__device__ float  g_sdot4[MROWS*4];      // per-(row, n-tile) partial  h.w_time
__device__ float  g_as[NROWS], g_bs[NROWS], g_ag[NROWS], g_bg[NROWS];
__device__ __half g_win_h[HH*HH];        // fp16 copy of w_in
__device__ __half g_wn_h[HH*HH];         // fp16 copy of w_noise

static __device__ __forceinline__ unsigned h2u(__half2 h){ return *reinterpret_cast<unsigned*>(&h); }

// ============================== K0: weight fp32->fp16 pre-convert ==============================
__global__ __launch_bounds__(256)
void k0_wconv(const float* __restrict__ win, const float* __restrict__ wnoise)
{
    int i = (blockIdx.x*256 + threadIdx.x) * 4;
    if (i < HH*HH){
        float4 a = *reinterpret_cast<const float4*>(&win[i]);
        float4 b = *reinterpret_cast<const float4*>(&wnoise[i]);
        __half2 a0 = __floats2half2_rn(a.x,a.y), a1 = __floats2half2_rn(a.z,a.w);
        __half2 b0 = __floats2half2_rn(b.x,b.y), b1 = __floats2half2_rn(b.z,b.w);
        uint2 va; va.x=h2u(a0); va.y=h2u(a1);
        uint2 vb; vb.x=h2u(b0); vb.y=h2u(b1);
        *reinterpret_cast<uint2*>(&g_win_h[i]) = va;
        *reinterpret_cast<uint2*>(&g_wn_h[i])  = vb;
    }
}

// ============================== K1: embeddings + per-event projections ==============================
__global__ __launch_bounds__(128)
void k1_embed(const int* __restrict__ etype, const float* __restrict__ etime,
              const float* __restrict__ wt, const float* __restrict__ table,
              const float* __restrict__ wsig, const float* __restrict__ wgate)
{
    int row = blockIdx.x;
    int j = threadIdx.x;          // 0..127
    int s = row & (SS-1);
    int ty = etype[row];
    float t = etime[row];
    float e0 = table[ty*DD + j];
    float e1 = table[ty*DD + 128 + j];
    const float kc = -9.210340371976184f / (float)DD;   // -ln(10000)/d
    float dt = __expf((float)(2*j) * kc);
    float arc = (float)s * dt + t * wt[j];
    size_t base = (size_t)row * HH;
    g_hv_h[base + j]       = __float2half_rn(sinf(arc));
    g_hv_h[base + 128 + j] = __float2half_rn(cosf(arc));
    g_hv_h[base + 256 + j] = __float2half_rn(e0);
    g_hv_h[base + 384 + j] = __float2half_rn(e1);
    float pas = e0*wsig[j]      + e1*wsig[128+j];
    float pbs = e0*wsig[256+j]  + e1*wsig[384+j];
    float pag = e0*wgate[j]     + e1*wgate[128+j];
    float pbg = e0*wgate[256+j] + e1*wgate[384+j];
    __shared__ float r4[4][4];
    #pragma unroll
    for (int o=16;o>0;o>>=1){
        pas += __shfl_xor_sync(0xffffffffu, pas, o);
        pbs += __shfl_xor_sync(0xffffffffu, pbs, o);
        pag += __shfl_xor_sync(0xffffffffu, pag, o);
        pbg += __shfl_xor_sync(0xffffffffu, pbg, o);
    }
    if ((j&31)==0){ int w=j>>5; r4[w][0]=pas; r4[w][1]=pbs; r4[w][2]=pag; r4[w][3]=pbg; }
    __syncthreads();
    if (j==0){
        g_as[row]=r4[0][0]+r4[1][0]+r4[2][0]+r4[3][0];
        g_bs[row]=r4[0][1]+r4[1][1]+r4[2][1]+r4[3][1];
        g_ag[row]=r4[0][2]+r4[1][2]+r4[2][2]+r4[3][2];
        g_bg[row]=r4[0][3]+r4[1][3]+r4[2][3]+r4[3][3];
    }
}

// ============================== K2: scores + aggregation via WMMA, j-split ==============================
// grid: (it 0..15, b 0..3, zz 0..3)  zz = hhalf | (jhalf<<1); block 256 (8 warps as 2x4)
__global__ __launch_bounds__(256)
void k2_aggregate(const float* __restrict__ etime)
{
    __shared__ __align__(16) __half Sh[64][72];
    __shared__ __align__(16) __half HV[64][264];
    __shared__ float asj[64], agj[64], tjv[64];
    __shared__ float bsi[64], bgi[64], tiv[64];

    const int tid = threadIdx.x;
    const int it = blockIdx.x;
    const int b  = blockIdx.y;
    const int hbase  = (blockIdx.z & 1) * 256;
    const int jhalf  = blockIdx.z >> 1;
    const int rowbase = b * SS;
    const int ibase = it * 64;

    if (tid < 64){
        int gi = rowbase + ibase + tid;
        bsi[tid]=g_bs[gi]; bgi[tid]=g_bg[gi]; tiv[tid]=etime[gi];
    }

    const int warp = tid>>5;
    const int wr = warp>>2;
    const int wc = warp&3;

    wmma::fragment<wmma::accumulator,16,16,16,float> acc[2][4];
    #pragma unroll
    for (int f=0;f<2;f++)
      #pragma unroll
      for (int g=0;g<4;g++) wmma::fill_fragment(acc[f][g], 0.f);

    const int il = tid>>2;
    const int jq = (tid&3)*16;
    const int hrow = tid>>2;
    const int hc4 = tid&3;

    const int j0 = jhalf * 8;
    const int j1 = jhalf ? it : ((it < 7) ? it : 7);

    for (int jt = j0; jt <= j1; jt++){
        if (tid < 64){
            int gj = rowbase + jt*64 + tid;
            asj[tid]=g_as[gj]; agj[tid]=g_ag[gj]; tjv[tid]=etime[gj];
        }
        __syncthreads();
        {
            const __half* src = &g_hv_h[(size_t)(rowbase + jt*64 + hrow)*HH + hbase];
            #pragma unroll
            for (int u=0;u<8;u++){
                int c16 = hc4 + u*4;
                unsigned sa = (unsigned)__cvta_generic_to_shared(&HV[hrow][c16*8]);
                asm volatile("cp.async.cg.shared.global [%0], [%1], 16;\n" :: "r"(sa), "l"(src + c16*8));
            }
            asm volatile("cp.async.commit_group;\n");
        }
        {
            float bs_i = bsi[il], bg_i = bgi[il], t_i = tiv[il];
            bool diag = (jt == it);
            #pragma unroll
            for (int q=0;q<16;q++){
                int jl = jq + q;
                float sv = 0.f;
                if (!diag || (jl < il)){
                    float xg = agj[jl] + bg_i;
                    float gate = 1.f/(1.f+__expf(-xg));
                    float xs = asj[jl] + bs_i;
                    float sig = (xs > 20.f) ? xs : log1pf(__expf(xs));
                    float dtv = fabsf(t_i - tjv[jl]);
                    sv = gate * __expf(-sig*dtv);
                }
                Sh[il][jl] = __float2half_rn(sv);
            }
        }
        asm volatile("cp.async.wait_group 0;\n");
        __syncthreads();
        #pragma unroll
        for (int kk=0;kk<4;kk++){
            wmma::fragment<wmma::matrix_a,16,16,16,__half,wmma::row_major> af[2];
            wmma::fragment<wmma::matrix_b,16,16,16,__half,wmma::row_major> bf[4];
            #pragma unroll
            for (int f=0;f<2;f++)
                wmma::load_matrix_sync(af[f], &Sh[wr*32 + f*16][kk*16], 72);
            #pragma unroll
            for (int g=0;g<4;g++)
                wmma::load_matrix_sync(bf[g], &HV[kk*16][wc*64 + g*16], 264);
            #pragma unroll
            for (int f=0;f<2;f++)
              #pragma unroll
              for (int g=0;g<4;g++)
                wmma::mma_sync(acc[f][g], af[f], bf[g], acc[f][g]);
        }
    }
    float* dst0 = jhalf ? g_hidden2 : g_hidden;
    #pragma unroll
    for (int f=0;f<2;f++)
      #pragma unroll
      for (int g=0;g<4;g++)
        wmma::store_matrix_sync(&dst0[(size_t)(rowbase + ibase + wr*32 + f*16)*HH + hbase + wc*64 + g*16],
                                acc[f][g], HH, wmma::mem_row_major);
}

// ============================== K3: LayerNorm + mark_probs softmax ==============================
__global__ __launch_bounds__(256)
void k3_ln_pred(const float* __restrict__ gamma, const float* __restrict__ beta,
                const float* __restrict__ wpred, float* __restrict__ out_probs)
{
    int row = blockIdx.x, tid = threadIdx.x, lane = tid&31, w = tid>>5;
    size_t base = (size_t)row*HH;
    float x0 = g_hidden[base+tid]     + g_hidden2[base+tid];
    float x1 = g_hidden[base+256+tid] + g_hidden2[base+256+tid];
    __shared__ float red[8];
    float sv = x0+x1;
    #pragma unroll
    for (int o=16;o>0;o>>=1) sv += __shfl_xor_sync(0xffffffffu, sv, o);
    if (lane==0) red[w]=sv;
    __syncthreads();
    float mu=0.f;
    #pragma unroll
    for (int i=0;i<8;i++) mu+=red[i];
    mu *= (1.f/HH);
    float d0=x0-mu, d1=x1-mu;
    float vv = d0*d0+d1*d1;
    __syncthreads();
    #pragma unroll
    for (int o=16;o>0;o>>=1) vv += __shfl_xor_sync(0xffffffffu, vv, o);
    if (lane==0) red[w]=vv;
    __syncthreads();
    float var=0.f;
    #pragma unroll
    for (int i=0;i<8;i++) var+=red[i];
    var *= (1.f/HH);
    float rstd = rsqrtf(var + 1e-6f);
    float hn0 = d0*rstd*gamma[tid] + beta[tid];
    float hn1 = d1*rstd*gamma[256+tid] + beta[256+tid];
    g_hn_h[base+tid]     = __float2half_rn(hn0);
    g_hn_h[base+256+tid] = __float2half_rn(hn1);
    float pl[NTY];
    #pragma unroll
    for (int o=0;o<NTY;o++)
        pl[o] = hn0*wpred[o*HH+tid] + hn1*wpred[o*HH+256+tid];
    __shared__ float lred[8][NTY];
    #pragma unroll
    for (int o=0;o<NTY;o++){
        float p = pl[o];
        #pragma unroll
        for (int s=16;s>0;s>>=1) p += __shfl_xor_sync(0xffffffffu, p, s);
        if (lane==0) lred[w][o]=p;
    }
    __syncthreads();
    if (tid < 32){
        float l = -1e30f;
        if (tid < NTY){
            l = 0.f;
            #pragma unroll
            for (int i=0;i<8;i++) l += lred[i][tid];
        }
        float mx = l;
        #pragma unroll
        for (int o=16;o>0;o>>=1) mx = fmaxf(mx, __shfl_xor_sync(0xffffffffu, mx, o));
        float e = (tid<NTY) ? expf(l-mx) : 0.f;
        float se = e;
        #pragma unroll
        for (int o=16;o>0;o>>=1) se += __shfl_xor_sync(0xffffffffu, se, o);
        if (tid<NTY) out_probs[(size_t)row*NTY + tid] = e/se;
    }
}

// ============================== K4/K5: fp16 WMMA GEMM, K-chunk 32 (R10-proven mainloop) ==============================
// REDUCE=false: A = g_hn_h (fp16, cp.async), Bh = g_win_h, write g_c
// REDUCE=true : A = noise (fp32 LDG->cvt),   Bh = g_wn_h,  barrier-light relu.w_time epilogue -> g_sdot4
template<bool REDUCE>
__global__ __launch_bounds__(256, 2)
void gemm_h(const float* __restrict__ A32, const float* __restrict__ wtime)
{
    __shared__ __align__(16) __half As[2][128][40];
    __shared__ __align__(16) __half Bs[2][128][40];
    __shared__ __align__(16) float slab[8][16][20];
    __shared__ float gcs[4][128];
    __shared__ float wts[128];
    __shared__ float sred[4][128];

    const __half* __restrict__ Bh = REDUCE ? g_wn_h : g_win_h;

    const int tid  = threadIdx.x;
    const int warp = tid>>5;
    const int lane = tid&31;
    const int wm = warp>>2;       // 0..1  (64 M-rows each)
    const int wn = warp&3;        // 0..3  (32 N-cols each)
    const int n_cta = blockIdx.x * 128;   // n fastest-varying: 4 n-tiles share A via L2
    const int m_cta = blockIdx.y * 128;

    const int r0 = tid >> 3;           // 0..31, A(fp32) rows r0+32*i
    const int cc = (tid & 7) * 4;      // A col within 32-chunk

    const int br = tid >> 2;           // 0..63, cp.async rows br, br+64
    const int bc = (tid & 3) * 8;      // cp.async cols (fp16, 16B)

    wmma::fragment<wmma::accumulator,16,16,16,float> acc[4][2];
    #pragma unroll
    for (int i=0;i<4;i++)
      #pragma unroll
      for (int jx=0;jx<2;jx++) wmma::fill_fragment(acc[i][jx], 0.f);

    float4 ra[4];

    // ---- prologue: chunk 0 ----
    #pragma unroll
    for (int i=0;i<2;i++){
        unsigned sb = (unsigned)__cvta_generic_to_shared(&Bs[0][br+64*i][bc]);
        asm volatile("cp.async.cg.shared.global [%0], [%1], 16;\n" :: "r"(sb), "l"(&Bh[(size_t)(n_cta + br + 64*i)*HH + bc]));
        if (!REDUCE){
            unsigned sa = (unsigned)__cvta_generic_to_shared(&As[0][br+64*i][bc]);
            asm volatile("cp.async.cg.shared.global [%0], [%1], 16;\n" :: "r"(sa), "l"(&g_hn_h[(size_t)(m_cta + br + 64*i)*HH + bc]));
        }
    }
    asm volatile("cp.async.commit_group;\n");
    if (REDUCE){
        #pragma unroll
        for (int i=0;i<4;i++)
            ra[i] = *reinterpret_cast<const float4*>(&A32[(size_t)(m_cta + r0 + 32*i)*HH + cc]);
        #pragma unroll
        for (int i=0;i<4;i++){
            __half2 a01 = __floats2half2_rn(ra[i].x, ra[i].y);
            __half2 a23 = __floats2half2_rn(ra[i].z, ra[i].w);
            uint2 va; va.x = h2u(a01); va.y = h2u(a23);
            *reinterpret_cast<uint2*>(&As[0][r0+32*i][cc]) = va;
        }
    }
    asm volatile("cp.async.wait_group 0;\n");
    __syncthreads();

    #pragma unroll 1
    for (int kc=0; kc<16; kc++){
        const int cur = kc & 1;
        const int nxt = cur ^ 1;
        if (kc < 15){
            int k0 = (kc+1)*32;
            #pragma unroll
            for (int i=0;i<2;i++){
                unsigned sb = (unsigned)__cvta_generic_to_shared(&Bs[nxt][br+64*i][bc]);
                asm volatile("cp.async.cg.shared.global [%0], [%1], 16;\n" :: "r"(sb), "l"(&Bh[(size_t)(n_cta + br + 64*i)*HH + k0 + bc]));
                if (!REDUCE){
                    unsigned sa = (unsigned)__cvta_generic_to_shared(&As[nxt][br+64*i][bc]);
                    asm volatile("cp.async.cg.shared.global [%0], [%1], 16;\n" :: "r"(sa), "l"(&g_hn_h[(size_t)(m_cta + br + 64*i)*HH + k0 + bc]));
                }
            }
            asm volatile("cp.async.commit_group;\n");
            if (REDUCE){
                #pragma unroll
                for (int i=0;i<4;i++)
                    ra[i] = *reinterpret_cast<const float4*>(&A32[(size_t)(m_cta + r0 + 32*i)*HH + k0 + cc]);
            }
        }
        #pragma unroll
        for (int ks=0; ks<2; ks++){
            wmma::fragment<wmma::matrix_a,16,16,16,__half,wmma::row_major> af[4];
            wmma::fragment<wmma::matrix_b,16,16,16,__half,wmma::col_major> bf[2];
            #pragma unroll
            for (int jx=0;jx<2;jx++)
                wmma::load_matrix_sync(bf[jx], &Bs[cur][wn*32 + jx*16][ks*16], 40);
            #pragma unroll
            for (int i=0;i<4;i++){
                wmma::load_matrix_sync(af[i], &As[cur][wm*64 + i*16][ks*16], 40);
                #pragma unroll
                for (int jx=0;jx<2;jx++)
                    wmma::mma_sync(acc[i][jx], af[i], bf[jx], acc[i][jx]);
            }
        }
        if (kc < 15){
            if (REDUCE){
                #pragma unroll
                for (int i=0;i<4;i++){
                    __half2 a01 = __floats2half2_rn(ra[i].x, ra[i].y);
                    __half2 a23 = __floats2half2_rn(ra[i].z, ra[i].w);
                    uint2 va; va.x = h2u(a01); va.y = h2u(a23);
                    *reinterpret_cast<uint2*>(&As[nxt][r0+32*i][cc]) = va;
                }
            }
            asm volatile("cp.async.wait_group 0;\n");
            __syncthreads();
        }
    }

    if (!REDUCE){
        #pragma unroll
        for (int i=0;i<4;i++)
          #pragma unroll
          for (int jx=0;jx<2;jx++)
            wmma::store_matrix_sync(&g_c[(size_t)(m_cta + wm*64 + i*16)*HH + n_cta + wn*32 + jx*16],
                                    acc[i][jx], HH, wmma::mem_row_major);
    } else {
        // ---- barrier-light epilogue: smem-preloaded g_c/wtime, warp-private slab drain ----
        const int bs0 = m_cta / NSAMP;
        if (tid < 128) wts[tid] = wtime[n_cta + tid];
        #pragma unroll
        for (int q=0;q<2;q++){
            int idx = q*256 + tid;               // 0..511 covers gcs[4][128]
            int bi = idx >> 7;
            int rowb = bs0 + bi; if (rowb > NROWS-1) rowb = NROWS-1;
            gcs[bi][idx & 127] = g_c[(size_t)rowb*HH + n_cta + (idx & 127)];
        }
        __syncthreads();

        const int r = lane >> 1;
        const int hsel = (lane & 1) * 8;
        #pragma unroll
        for (int i=0;i<4;i++){
            int rloc = wm*64 + i*16 + r;
            int bi = (m_cta + rloc) / NSAMP - bs0;
            float vacc = 0.f;
            #pragma unroll
            for (int jx=0;jx<2;jx++){
                wmma::store_matrix_sync(&slab[warp][0][0], acc[i][jx], 20, wmma::mem_row_major);
                __syncwarp();
                #pragma unroll
                for (int c=0;c<8;c++){
                    int col = wn*32 + jx*16 + hsel + c;
                    float h = slab[warp][r][hsel + c] + gcs[bi][col];
                    vacc += fmaxf(h, 0.f) * wts[col];
                }
                __syncwarp();
            }
            vacc += __shfl_xor_sync(0xffffffffu, vacc, 1);
            if ((lane & 1) == 0) sred[wn][rloc] = vacc;
        }
        __syncthreads();
        if (tid < 128)
            g_sdot4[(size_t)(m_cta + tid)*4 + blockIdx.x] =
                (sred[0][tid] + sred[1][tid]) + (sred[2][tid] + sred[3][tid]);
    }
}

// ============================== K6: softplus + mean over samples ==============================
__global__ void k6_pred(float* __restrict__ out)
{
    int bs = blockIdx.x*blockDim.x + threadIdx.x;
    if (bs >= NROWS) return;
    float acc = 0.f;
    for (int n=0;n<NSAMP;n++){
        const float4 v = *reinterpret_cast<const float4*>(&g_sdot4[(size_t)(bs*NSAMP+n)*4]);
        float x = (v.x+v.y)+(v.z+v.w);
        float sp = (x > 20.f) ? x : log1pf(expf(x));
        acc += sp;
    }
    out[bs] = acc * (1.f/NSAMP);
}

// ============================== launch ==============================
extern "C" void kernel_launch(void* const* d_in, const int* in_sizes, int n_in,
                              void* d_out, int out_size) {
    const int*   etype  = (const int*)  d_in[0];
    const float* etime  = (const float*)d_in[1];
    const float* noise  = (const float*)d_in[2];
    const float* wt     = (const float*)d_in[3];
    const float* table  = (const float*)d_in[4];
    const float* wsig   = (const float*)d_in[5];
    const float* wgate  = (const float*)d_in[6];
    const float* lng    = (const float*)d_in[7];
    const float* lnb    = (const float*)d_in[8];
    const float* wpred  = (const float*)d_in[9];
    const float* win    = (const float*)d_in[10];
    const float* wnoise = (const float*)d_in[11];
    const float* wtime  = (const float*)d_in[12];
    float* out = (float*)d_out;

    k0_wconv<<<HH*HH/(256*4),256>>>(win, wnoise);
    k1_embed<<<NROWS,128>>>(etype, etime, wt, table, wsig, wgate);
    k2_aggregate<<<dim3(16,BB,4),256>>>(etime);
    k3_ln_pred<<<NROWS,256>>>(lng, lnb, wpred, out + NROWS);
    gemm_h<false><<<dim3(4, NROWS/128),256>>>(nullptr, nullptr);
    gemm_h<true ><<<dim3(4, MROWS/128),256>>>(noise, wtime);
    k6_pred<<<NROWS/128,128>>>(out);
}